// round 2
// baseline (speedup 1.0000x reference)
#include <cuda_runtime.h>
#include <cuda_bf16.h>
#include <math.h>

// Problem constants
#define BB   4
#define HW   4096          // 64*64
#define CC   512
#define GG   32
#define CPG  16            // channels per group
#define NPIX (BB*HW)       // 16384
#define EPS  1e-5f

// ---------------- scratch (static device globals; no allocations) -------------
__device__ float g_xn [ (long)NPIX*CC ];
__device__ float g_q  [ (long)NPIX*CC ];
__device__ float g_k  [ (long)NPIX*CC ];
__device__ float g_v  [ (long)NPIX*CC ];
__device__ float g_att[ (long)NPIX*CC ];
__device__ float g_sc [ (long)BB*HW*HW ];   // 256 MB scores / attn (in-place softmax)
__device__ float g_mean[BB*GG];
__device__ float g_rstd[BB*GG];

// ---------------- GroupNorm stats: one block per (b,g) -----------------------
__global__ void gn_stats(const float* __restrict__ x,
                         float* __restrict__ meanOut, float* __restrict__ rstdOut)
{
    int bg = blockIdx.x;            // 0..127
    int b  = bg >> 5;
    int g  = bg & 31;
    const float* base = x + (long)b*HW*CC + g*CPG;
    int tid = threadIdx.x;

    float s = 0.f, ss = 0.f;
    for (int p = tid; p < HW; p += 256) {
        const float4* q4 = (const float4*)(base + (long)p*CC);
        #pragma unroll
        for (int i = 0; i < 4; i++) {
            float4 t = q4[i];
            s  += t.x + t.y + t.z + t.w;
            ss += t.x*t.x + t.y*t.y + t.z*t.z + t.w*t.w;
        }
    }
    __shared__ float rs[256], rss[256];
    rs[tid] = s; rss[tid] = ss;
    __syncthreads();
    for (int st = 128; st > 0; st >>= 1) {
        if (tid < st) { rs[tid] += rs[tid+st]; rss[tid] += rss[tid+st]; }
        __syncthreads();
    }
    if (tid == 0) {
        const float inv = 1.f / (float)(HW*CPG);
        float m   = rs[0] * inv;
        float var = rss[0] * inv - m*m;
        meanOut[bg] = m;
        rstdOut[bg] = rsqrtf(var + EPS);
    }
}

// ---------------- GroupNorm apply (vectorized) --------------------------------
__global__ void gn_apply(const float* __restrict__ x,
                         const float* __restrict__ gamma, const float* __restrict__ beta,
                         const float* __restrict__ mean,  const float* __restrict__ rstd,
                         float* __restrict__ xn)
{
    long idx = (long)blockIdx.x*256 + threadIdx.x;   // float4 index
    int  c4  = (int)(idx & 127) * 4;                 // channel of .x
    long row = idx >> 7;                             // b*HW + p
    int  b   = (int)(row >> 12);
    int  g   = c4 >> 4;
    float m = mean[b*GG + g];
    float r = rstd[b*GG + g];
    float4 xv = ((const float4*)x)[idx];
    float4 gv = ((const float4*)gamma)[c4 >> 2];
    float4 bv = ((const float4*)beta )[c4 >> 2];
    float4 o;
    o.x = (xv.x - m)*r*gv.x + bv.x;
    o.y = (xv.y - m)*r*gv.y + bv.y;
    o.z = (xv.z - m)*r*gv.z + bv.z;
    o.w = (xv.w - m)*r*gv.w + bv.w;
    ((float4*)xn)[idx] = o;
}

// ---------------- generic tiled SGEMM -----------------------------------------
// C[M,N] = scale * A[M,K] @ (TRANSB ? B[N,K]^T : B[K,N]) (+bias) (+residual)
// All of M,N divisible by 64; K divisible by 16. 16x16 threads, 4x4 microtile.
template<bool TRANSB>
__global__ void sgemm(const float* __restrict__ A, const float* __restrict__ B,
                      float* __restrict__ C,
                      int M, int N, int K,
                      long sA, long sB, long sC,
                      const float* __restrict__ bias,
                      const float* __restrict__ res, long sRes,
                      float scale)
{
    __shared__ float As[16][64];   // k-major
    __shared__ float Bs[16][64];   // k-major

    int z = blockIdx.z;
    A += sA * z;  B += sB * z;  C += sC * z;

    int bm = blockIdx.y * 64;
    int bn = blockIdx.x * 64;
    int tid = threadIdx.y * 16 + threadIdx.x;

    float acc[4][4] = {};

    for (int k0 = 0; k0 < K; k0 += 16) {
        {   // A tile: 64(m) x 16(k), float4 over k, store transposed
            int m  = tid >> 2;
            int kk = (tid & 3) * 4;
            float4 a = *(const float4*)(A + (long)(bm + m)*K + k0 + kk);
            As[kk+0][m] = a.x; As[kk+1][m] = a.y; As[kk+2][m] = a.z; As[kk+3][m] = a.w;
        }
        if (TRANSB) {   // B[N,K]: load rows (k contiguous), store transposed
            int n  = tid >> 2;
            int kk = (tid & 3) * 4;
            float4 b = *(const float4*)(B + (long)(bn + n)*K + k0 + kk);
            Bs[kk+0][n] = b.x; Bs[kk+1][n] = b.y; Bs[kk+2][n] = b.z; Bs[kk+3][n] = b.w;
        } else {        // B[K,N]: n contiguous
            int kk = tid >> 4;
            int n  = (tid & 15) * 4;
            *(float4*)&Bs[kk][n] = *(const float4*)(B + (long)(k0 + kk)*N + bn + n);
        }
        __syncthreads();

        #pragma unroll
        for (int kk = 0; kk < 16; kk++) {
            float4 a = *(float4*)&As[kk][threadIdx.y * 4];
            float4 b = *(float4*)&Bs[kk][threadIdx.x * 4];
            acc[0][0] += a.x*b.x; acc[0][1] += a.x*b.y; acc[0][2] += a.x*b.z; acc[0][3] += a.x*b.w;
            acc[1][0] += a.y*b.x; acc[1][1] += a.y*b.y; acc[1][2] += a.y*b.z; acc[1][3] += a.y*b.w;
            acc[2][0] += a.z*b.x; acc[2][1] += a.z*b.y; acc[2][2] += a.z*b.z; acc[2][3] += a.z*b.w;
            acc[3][0] += a.w*b.x; acc[3][1] += a.w*b.y; acc[3][2] += a.w*b.z; acc[3][3] += a.w*b.w;
        }
        __syncthreads();
    }

    #pragma unroll
    for (int i = 0; i < 4; i++) {
        int row = bm + threadIdx.y * 4 + i;
        #pragma unroll
        for (int j = 0; j < 4; j++) {
            int col = bn + threadIdx.x * 4 + j;
            float v = acc[i][j] * scale;
            if (bias) v += bias[col];
            if (res)  v += res[sRes * z + (long)row * N + col];
            C[(long)row * N + col] = v;
        }
    }
}

// ---------------- row softmax: one block per row of 4096 ----------------------
__global__ void softmax_rows(float* __restrict__ S)
{
    float* p = S + (long)blockIdx.x * HW;
    int tid = threadIdx.x;   // 256

    float4 v[4];
    float mx = -1e30f;
    #pragma unroll
    for (int i = 0; i < 4; i++) {
        v[i] = ((float4*)p)[tid + i * 256];
        mx = fmaxf(mx, fmaxf(fmaxf(v[i].x, v[i].y), fmaxf(v[i].z, v[i].w)));
    }
    __shared__ float red[256];
    red[tid] = mx;
    __syncthreads();
    for (int s = 128; s > 0; s >>= 1) {
        if (tid < s) red[tid] = fmaxf(red[tid], red[tid + s]);
        __syncthreads();
    }
    mx = red[0];
    __syncthreads();

    float sum = 0.f;
    #pragma unroll
    for (int i = 0; i < 4; i++) {
        v[i].x = __expf(v[i].x - mx);
        v[i].y = __expf(v[i].y - mx);
        v[i].z = __expf(v[i].z - mx);
        v[i].w = __expf(v[i].w - mx);
        sum += v[i].x + v[i].y + v[i].z + v[i].w;
    }
    red[tid] = sum;
    __syncthreads();
    for (int s = 128; s > 0; s >>= 1) {
        if (tid < s) red[tid] += red[tid + s];
        __syncthreads();
    }
    float inv = 1.f / red[0];

    #pragma unroll
    for (int i = 0; i < 4; i++) {
        v[i].x *= inv; v[i].y *= inv; v[i].z *= inv; v[i].w *= inv;
        ((float4*)p)[tid + i * 256] = v[i];
    }
}

// ---------------- host launcher ------------------------------------------------
extern "C" void kernel_launch(void* const* d_in, const int* in_sizes, int n_in,
                              void* d_out, int out_size)
{
    const float* x     = (const float*)d_in[0];
    const float* gamma = (const float*)d_in[1];
    const float* beta  = (const float*)d_in[2];
    const float* Wq    = (const float*)d_in[3];
    const float* bq    = (const float*)d_in[4];
    const float* Wk    = (const float*)d_in[5];
    const float* bk    = (const float*)d_in[6];
    const float* Wv    = (const float*)d_in[7];
    const float* bv    = (const float*)d_in[8];
    const float* Wp    = (const float*)d_in[9];
    const float* bp    = (const float*)d_in[10];
    float* out = (float*)d_out;

    static float *xn=nullptr, *q=nullptr, *k=nullptr, *v=nullptr,
                 *att=nullptr, *sc=nullptr, *mean=nullptr, *rstd=nullptr;
    if (!xn) {
        cudaGetSymbolAddress((void**)&xn,   g_xn);
        cudaGetSymbolAddress((void**)&q,    g_q);
        cudaGetSymbolAddress((void**)&k,    g_k);
        cudaGetSymbolAddress((void**)&v,    g_v);
        cudaGetSymbolAddress((void**)&att,  g_att);
        cudaGetSymbolAddress((void**)&sc,   g_sc);
        cudaGetSymbolAddress((void**)&mean, g_mean);
        cudaGetSymbolAddress((void**)&rstd, g_rstd);
    }

    const float scale = 0.044194173824159216f;  // 1/sqrt(512)
    dim3 tb(16, 16);

    // GroupNorm
    gn_stats<<<BB*GG, 256>>>(x, mean, rstd);
    gn_apply<<<(NPIX*CC/4 + 255)/256, 256>>>(x, gamma, beta, mean, rstd, xn);

    // Q, K, V projections: [16384,512] @ [512,512] + bias
    sgemm<false><<<dim3(CC/64, NPIX/64, 1), tb>>>(xn, Wq, q, NPIX, CC, CC, 0,0,0, bq, nullptr, 0, 1.f);
    sgemm<false><<<dim3(CC/64, NPIX/64, 1), tb>>>(xn, Wk, k, NPIX, CC, CC, 0,0,0, bk, nullptr, 0, 1.f);
    sgemm<false><<<dim3(CC/64, NPIX/64, 1), tb>>>(xn, Wv, v, NPIX, CC, CC, 0,0,0, bv, nullptr, 0, 1.f);

    // scores = (Q @ K^T) * scale, per-batch
    sgemm<true><<<dim3(HW/64, HW/64, BB), tb>>>(q, k, sc, HW, HW, CC,
                                               (long)HW*CC, (long)HW*CC, (long)HW*HW,
                                               nullptr, nullptr, 0, scale);

    // softmax rows
    softmax_rows<<<BB*HW, 256>>>(sc);

    // out = attn @ V, per-batch
    sgemm<false><<<dim3(CC/64, HW/64, BB), tb>>>(sc, v, att, HW, CC, HW,
                                                (long)HW*HW, (long)HW*CC, (long)HW*CC,
                                                nullptr, nullptr, 0, 1.f);

    // proj + bias + residual
    sgemm<false><<<dim3(CC/64, NPIX/64, 1), tb>>>(att, Wp, out, NPIX, CC, CC, 0,0,0,
                                                  bp, x, 0, 1.f);
}

// round 5
// speedup vs baseline: 7.1795x; 7.1795x over previous
#include <cuda_runtime.h>
#include <cuda_bf16.h>
#include <cstdint>
#include <math.h>

typedef __nv_bfloat16 bf16;

#define BB   4
#define HW   4096
#define CC   512
#define GG   32
#define CPG  16
#define NPIX 16384
#define EPS  1e-5f

// scratch
__device__ bf16  g_xn [(long)NPIX*CC];
__device__ bf16  g_q  [(long)NPIX*CC];
__device__ bf16  g_k  [(long)NPIX*CC];
__device__ bf16  g_vt [(long)CC*NPIX];
__device__ bf16  g_att[(long)NPIX*CC];
__device__ bf16  g_sc [(long)BB*HW*HW];
__device__ bf16  g_wqt[CC*CC], g_wkt[CC*CC], g_wvt[CC*CC], g_wpt[CC*CC];
__device__ float g_mean[BB*GG], g_rstd[BB*GG];

__device__ __forceinline__ uint32_t smem_u32(const void* p) {
    uint32_t a;
    asm("{ .reg .u64 t; cvta.to.shared.u64 t, %1; cvt.u32.u64 %0, t; }" : "=r"(a) : "l"(p));
    return a;
}
#define CP16(s, g) asm volatile("cp.async.cg.shared.global [%0], [%1], 16;" :: "r"(s), "l"(g) : "memory")
#define CP_COMMIT() asm volatile("cp.async.commit_group;" ::: "memory")
#define CP_WAIT(n)  asm volatile("cp.async.wait_group %0;" :: "n"(n) : "memory")
#define LDSM4(r0,r1,r2,r3,a) asm volatile( \
    "ldmatrix.sync.aligned.m8n8.x4.shared.b16 {%0,%1,%2,%3}, [%4];" \
    : "=r"(r0),"=r"(r1),"=r"(r2),"=r"(r3) : "r"(a))
#define MMA16816(c0,c1,c2,c3,a0,a1,a2,a3,b0,b1) asm volatile( \
    "mma.sync.aligned.m16n8k16.row.col.f32.bf16.bf16.f32 " \
    "{%0,%1,%2,%3}, {%4,%5,%6,%7}, {%8,%9}, {%0,%1,%2,%3};" \
    : "+f"(c0),"+f"(c1),"+f"(c2),"+f"(c3) \
    : "r"(a0),"r"(a1),"r"(a2),"r"(a3),"r"(b0),"r"(b1))

// ---------------- GroupNorm ---------------------------------------------------
__global__ void gn_stats(const float* __restrict__ x, float* __restrict__ mo, float* __restrict__ ro)
{
    int bg = blockIdx.x, b = bg >> 5, g = bg & 31;
    const float* base = x + (long)b*HW*CC + g*CPG;
    int tid = threadIdx.x;
    float s = 0.f, ss = 0.f;
    for (int p = tid; p < HW; p += 256) {
        const float4* q4 = (const float4*)(base + (long)p*CC);
        #pragma unroll
        for (int i = 0; i < 4; i++) {
            float4 t = q4[i];
            s  += t.x + t.y + t.z + t.w;
            ss += t.x*t.x + t.y*t.y + t.z*t.z + t.w*t.w;
        }
    }
    __shared__ float rs[256], rss[256];
    rs[tid] = s; rss[tid] = ss;
    __syncthreads();
    for (int st = 128; st > 0; st >>= 1) {
        if (tid < st) { rs[tid] += rs[tid+st]; rss[tid] += rss[tid+st]; }
        __syncthreads();
    }
    if (tid == 0) {
        const float inv = 1.f / (float)(HW*CPG);
        float m = rs[0]*inv, var = rss[0]*inv - m*m;
        mo[bg] = m; ro[bg] = rsqrtf(var + EPS);
    }
}

__global__ void gn_apply(const float* __restrict__ x, const float* __restrict__ gamma,
                         const float* __restrict__ beta, const float* __restrict__ mean,
                         const float* __restrict__ rstd, bf16* __restrict__ xn)
{
    long idx = (long)blockIdx.x*256 + threadIdx.x;
    int  c4  = (int)(idx & 127) * 4;
    int  b   = (int)(idx >> 19);
    int  g   = c4 >> 4;
    float m = mean[b*GG + g], r = rstd[b*GG + g];
    float4 xv = ((const float4*)x)[idx];
    float4 gv = ((const float4*)gamma)[c4 >> 2];
    float4 bv = ((const float4*)beta )[c4 >> 2];
    __nv_bfloat162 o0 = __floats2bfloat162_rn((xv.x-m)*r*gv.x + bv.x, (xv.y-m)*r*gv.y + bv.y);
    __nv_bfloat162 o1 = __floats2bfloat162_rn((xv.z-m)*r*gv.z + bv.z, (xv.w-m)*r*gv.w + bv.w);
    uint2 o; o.x = *(uint32_t*)&o0; o.y = *(uint32_t*)&o1;
    ((uint2*)xn)[idx] = o;
}

// weight transpose fp32 -> bf16:  WT[d][c] = W[c][d]
__global__ void wtrans(const float* __restrict__ W, bf16* __restrict__ WT)
{
    __shared__ float t[32][33];
    int bx = blockIdx.x*32, by = blockIdx.y*32;
    int x = threadIdx.x, y = threadIdx.y;
    #pragma unroll
    for (int i = 0; i < 32; i += 8) t[y+i][x] = W[(long)(by+y+i)*CC + bx + x];
    __syncthreads();
    #pragma unroll
    for (int i = 0; i < 32; i += 8) WT[(long)(bx+y+i)*CC + by + x] = __float2bfloat16(t[x][y+i]);
}

// ---------------- mma.sync bf16 GEMM: C[M,N] = scale*A@B^T (+bias/res) ---------
// A[M,K] row-major (ldA), B[N,K] row-major (ldB). Tile 128x128, K-step 32.
// 8 warps: warp_m = wid>>2 (64 rows), warp_n = wid&3 (32 cols).
#define TM 128
#define TN 128
#define TK 32
#define STAGES 4
#define ROWB 80                    // padded row stride bytes (32 bf16 = 64B + 16 pad)
#define A_SZ (128*ROWB)            // 10240
#define STGB (2*A_SZ)              // 20480
#define GEMM_DSMEM (STAGES*STGB)   // 81920

__global__ void __launch_bounds__(256)
gemm_mma(const bf16* __restrict__ A, const bf16* __restrict__ B,
         long ldA, long ldB, int kChunks,
         int aRowMul, int bRowMul, long bKMul,
         void* __restrict__ Cout, long ldC, long cZStride, int outF32,
         const float* __restrict__ colBias, const float* __restrict__ rowBias,
         const float* __restrict__ res, float scale)
{
    extern __shared__ char dyn[];
    uint32_t smem0 = smem_u32(dyn);
    int tid = threadIdx.x, wid = tid >> 5, lane = tid & 31;
    int warp_m = wid >> 2, warp_n = wid & 3;
    int z = blockIdx.z;
    long bm = (long)blockIdx.y * TM;
    long bn = (long)blockIdx.x * TN;

    const bf16* baseA = A + ((long)z*aRowMul + bm) * ldA;
    const bf16* baseB = B + ((long)z*bRowMul + bn) * ldB + (long)z*bKMul;

    // per-thread load indices (2 chunks for A, 2 for B per stage)
    int lr0 = tid >> 2,        lc0 = tid & 3;
    int lr1 = (tid+256) >> 2,  lc1 = (tid+256) & 3;

    // ldmatrix lane offsets (bytes within stage region)
    uint32_t aoff[4], boff[2];
    #pragma unroll
    for (int mt = 0; mt < 4; mt++)
        aoff[mt] = (uint32_t)((warp_m*64 + mt*16 + (lane & 15))*ROWB + (lane >> 4)*16);
    #pragma unroll
    for (int np = 0; np < 2; np++)
        boff[np] = (uint32_t)((warp_n*32 + np*16 + ((lane >> 4) & 1)*8 + (lane & 7))*ROWB
                              + ((lane >> 3) & 1)*16);

    float acc[4][4][4];
    #pragma unroll
    for (int i = 0; i < 4; i++)
        #pragma unroll
        for (int j = 0; j < 4; j++)
            #pragma unroll
            for (int r = 0; r < 4; r++) acc[i][j][r] = 0.f;

    // prologue: issue STAGES-1 stages
    #pragma unroll
    for (int s = 0; s < STAGES-1; s++) {
        if (s < kChunks) {
            uint32_t sA = smem0 + s*STGB, sB = sA + A_SZ;
            const bf16* Ap = baseA + (long)s*TK;
            const bf16* Bp = baseB + (long)s*TK;
            CP16(sA + lr0*ROWB + lc0*16, Ap + (long)lr0*ldA + lc0*8);
            CP16(sA + lr1*ROWB + lc1*16, Ap + (long)lr1*ldA + lc1*8);
            CP16(sB + lr0*ROWB + lc0*16, Bp + (long)lr0*ldB + lc0*8);
            CP16(sB + lr1*ROWB + lc1*16, Bp + (long)lr1*ldB + lc1*8);
        }
        CP_COMMIT();
    }

    for (int c = 0; c < kChunks; c++) {
        CP_WAIT(STAGES-2);
        __syncthreads();

        int nx = c + STAGES - 1;
        if (nx < kChunks) {
            int s = nx & (STAGES-1);
            uint32_t sA = smem0 + s*STGB, sB = sA + A_SZ;
            const bf16* Ap = baseA + (long)nx*TK;
            const bf16* Bp = baseB + (long)nx*TK;
            CP16(sA + lr0*ROWB + lc0*16, Ap + (long)lr0*ldA + lc0*8);
            CP16(sA + lr1*ROWB + lc1*16, Ap + (long)lr1*ldA + lc1*8);
            CP16(sB + lr0*ROWB + lc0*16, Bp + (long)lr0*ldB + lc0*8);
            CP16(sB + lr1*ROWB + lc1*16, Bp + (long)lr1*ldB + lc1*8);
        }
        CP_COMMIT();

        uint32_t sA = smem0 + (c & (STAGES-1))*STGB;
        uint32_t sB = sA + A_SZ;
        #pragma unroll
        for (int kp = 0; kp < 2; kp++) {
            uint32_t a[16], b[8];
            #pragma unroll
            for (int mt = 0; mt < 4; mt++)
                LDSM4(a[mt*4], a[mt*4+1], a[mt*4+2], a[mt*4+3], sA + aoff[mt] + kp*32);
            #pragma unroll
            for (int np = 0; np < 2; np++)
                LDSM4(b[np*4], b[np*4+1], b[np*4+2], b[np*4+3], sB + boff[np] + kp*32);
            #pragma unroll
            for (int mt = 0; mt < 4; mt++)
                #pragma unroll
                for (int nt = 0; nt < 4; nt++) {
                    int bi = (nt >> 1)*4 + (nt & 1)*2;
                    MMA16816(acc[mt][nt][0], acc[mt][nt][1], acc[mt][nt][2], acc[mt][nt][3],
                             a[mt*4], a[mt*4+1], a[mt*4+2], a[mt*4+3], b[bi], b[bi+1]);
                }
        }
    }
    CP_WAIT(0);
    __syncthreads();

    // ---------------- epilogue: regs -> smem -> coalesced gmem -----------------
    int rbase = warp_m*64 + (lane >> 2);
    int cbase = warp_n*32 + (lane & 3)*2;

    if (!outF32) {
        const int RS = TN*2 + 16;   // 272B
        #pragma unroll
        for (int mt = 0; mt < 4; mt++)
            #pragma unroll
            for (int nt = 0; nt < 4; nt++) {
                int col = cbase + nt*8;
                float cb0 = colBias ? colBias[bn + col]     : 0.f;
                float cb1 = colBias ? colBias[bn + col + 1] : 0.f;
                #pragma unroll
                for (int h = 0; h < 2; h++) {
                    int row = rbase + mt*16 + h*8;
                    float rb = rowBias ? rowBias[bm + row] : 0.f;
                    float v0 = acc[mt][nt][2*h]  *scale + rb + cb0;
                    float v1 = acc[mt][nt][2*h+1]*scale + rb + cb1;
                    *(__nv_bfloat162*)(dyn + row*RS + col*2) = __floats2bfloat162_rn(v0, v1);
                }
            }
        __syncthreads();
        bf16* C = (bf16*)Cout + (long)z*cZStride + bm*ldC + bn;
        #pragma unroll
        for (int it = 0; it < 8; it++) {
            int m = tid + it*256;           // 2048 16B-chunks
            int r = m >> 4, i = m & 15;
            *(uint4*)(C + (long)r*ldC + i*8) = *(uint4*)(dyn + r*RS + i*16);
        }
    } else {
        const int RS = TN*4 + 16;   // 528B
        #pragma unroll
        for (int mt = 0; mt < 4; mt++)
            #pragma unroll
            for (int nt = 0; nt < 4; nt++) {
                int col = cbase + nt*8;
                float cb0 = colBias ? colBias[bn + col]     : 0.f;
                float cb1 = colBias ? colBias[bn + col + 1] : 0.f;
                #pragma unroll
                for (int h = 0; h < 2; h++) {
                    int row = rbase + mt*16 + h*8;
                    float rb = rowBias ? rowBias[bm + row] : 0.f;
                    float2 v;
                    v.x = acc[mt][nt][2*h]  *scale + rb + cb0;
                    v.y = acc[mt][nt][2*h+1]*scale + rb + cb1;
                    *(float2*)(dyn + row*RS + col*4) = v;
                }
            }
        __syncthreads();
        float* C = (float*)Cout + (long)z*cZStride + bm*ldC + bn;
        const float* R = res ? res + (long)z*cZStride + bm*ldC + bn : nullptr;
        #pragma unroll
        for (int it = 0; it < 16; it++) {
            int m = tid + it*256;           // 4096 16B-chunks
            int r = m >> 5, i = m & 31;
            float4 v = *(float4*)(dyn + r*RS + i*16);
            if (R) {
                float4 rr = *(const float4*)(R + (long)r*ldC + i*4);
                v.x += rr.x; v.y += rr.y; v.z += rr.z; v.w += rr.w;
            }
            *(float4*)(C + (long)r*ldC + i*4) = v;
        }
    }
}

// ---------------- softmax over bf16 rows of 4096 -------------------------------
__global__ void softmax_bf16(bf16* __restrict__ S)
{
    bf16* p = S + (long)blockIdx.x * HW;
    int tid = threadIdx.x;               // 256 threads * 16 elems
    uint4 u[2];
    u[0] = ((uint4*)p)[2*tid];
    u[1] = ((uint4*)p)[2*tid + 1];
    float v[16];
    #pragma unroll
    for (int i = 0; i < 8; i++) {
        __nv_bfloat162 h = ((__nv_bfloat162*)u)[i];
        v[2*i] = __low2float(h); v[2*i+1] = __high2float(h);
    }
    float mx = -1e30f;
    #pragma unroll
    for (int i = 0; i < 16; i++) mx = fmaxf(mx, v[i]);
    __shared__ float red[256];
    red[tid] = mx; __syncthreads();
    for (int s = 128; s > 0; s >>= 1) {
        if (tid < s) red[tid] = fmaxf(red[tid], red[tid+s]);
        __syncthreads();
    }
    mx = red[0]; __syncthreads();
    float sum = 0.f;
    #pragma unroll
    for (int i = 0; i < 16; i++) { v[i] = __expf(v[i] - mx); sum += v[i]; }
    red[tid] = sum; __syncthreads();
    for (int s = 128; s > 0; s >>= 1) {
        if (tid < s) red[tid] += red[tid+s];
        __syncthreads();
    }
    float inv = 1.f / red[0];
    #pragma unroll
    for (int i = 0; i < 8; i++)
        ((__nv_bfloat162*)u)[i] = __floats2bfloat162_rn(v[2*i]*inv, v[2*i+1]*inv);
    ((uint4*)p)[2*tid]     = u[0];
    ((uint4*)p)[2*tid + 1] = u[1];
}

// ---------------- host -----------------------------------------------------------
extern "C" void kernel_launch(void* const* d_in, const int* in_sizes, int n_in,
                              void* d_out, int out_size)
{
    const float* x     = (const float*)d_in[0];
    const float* gamma = (const float*)d_in[1];
    const float* beta  = (const float*)d_in[2];
    const float* Wq    = (const float*)d_in[3];
    const float* bq    = (const float*)d_in[4];
    const float* Wk    = (const float*)d_in[5];
    const float* bk    = (const float*)d_in[6];
    const float* Wv    = (const float*)d_in[7];
    const float* bv    = (const float*)d_in[8];
    const float* Wp    = (const float*)d_in[9];
    const float* bp    = (const float*)d_in[10];
    float* out = (float*)d_out;

    static bf16 *xn=nullptr, *q=nullptr, *k=nullptr, *vt=nullptr, *att=nullptr, *sc=nullptr;
    static bf16 *wqt=nullptr, *wkt=nullptr, *wvt=nullptr, *wpt=nullptr;
    static float *mean=nullptr, *rstd=nullptr;
    if (!xn) {
        cudaGetSymbolAddress((void**)&xn,  g_xn);  cudaGetSymbolAddress((void**)&q,   g_q);
        cudaGetSymbolAddress((void**)&k,   g_k);   cudaGetSymbolAddress((void**)&vt,  g_vt);
        cudaGetSymbolAddress((void**)&att, g_att); cudaGetSymbolAddress((void**)&sc,  g_sc);
        cudaGetSymbolAddress((void**)&wqt, g_wqt); cudaGetSymbolAddress((void**)&wkt, g_wkt);
        cudaGetSymbolAddress((void**)&wvt, g_wvt); cudaGetSymbolAddress((void**)&wpt, g_wpt);
        cudaGetSymbolAddress((void**)&mean, g_mean); cudaGetSymbolAddress((void**)&rstd, g_rstd);
        cudaFuncSetAttribute(gemm_mma, cudaFuncAttributeMaxDynamicSharedMemorySize, GEMM_DSMEM);
    }

    const float scale = 0.044194173824159216f;   // 1/sqrt(512)

    gn_stats<<<BB*GG, 256>>>(x, mean, rstd);
    gn_apply<<<NPIX*CC/4/256, 256>>>(x, gamma, beta, mean, rstd, xn);

    dim3 wtb(32, 8), wtg(16, 16);
    wtrans<<<wtg, wtb>>>(Wq, wqt);
    wtrans<<<wtg, wtb>>>(Wk, wkt);
    wtrans<<<wtg, wtb>>>(Wv, wvt);
    wtrans<<<wtg, wtb>>>(Wp, wpt);

    // q = xn @ Wq + bq (bf16), k likewise
    gemm_mma<<<dim3(CC/TN, NPIX/TM, 1), 256, GEMM_DSMEM>>>(
        xn, wqt, CC, CC, CC/TK, 0, 0, 0, q, CC, 0, 0, bq, nullptr, nullptr, 1.f);
    gemm_mma<<<dim3(CC/TN, NPIX/TM, 1), 256, GEMM_DSMEM>>>(
        xn, wkt, CC, CC, CC/TK, 0, 0, 0, k, CC, 0, 0, bk, nullptr, nullptr, 1.f);
    // vt[c][bp] = Wv^T c . xn bp  (+bv as rowBias); vt is [512][16384]
    gemm_mma<<<dim3(NPIX/TN, CC/TM, 1), 256, GEMM_DSMEM>>>(
        wvt, xn, CC, CC, CC/TK, 0, 0, 0, vt, NPIX, 0, 0, nullptr, bv, nullptr, 1.f);

    // scores = scale * q @ k^T per batch (bf16)
    gemm_mma<<<dim3(HW/TN, HW/TM, BB), 256, GEMM_DSMEM>>>(
        q, k, CC, CC, CC/TK, HW, HW, 0, sc, HW, (long)HW*HW, 0,
        nullptr, nullptr, nullptr, scale);

    softmax_bf16<<<BB*HW, 256>>>(sc);

    // att = P @ V per batch: A = probs (ldA=HW), B = vt rows=channels, K offset z*HW
    gemm_mma<<<dim3(CC/TN, HW/TM, BB), 256, GEMM_DSMEM>>>(
        sc, vt, HW, NPIX, HW/TK, HW, 0, HW, att, CC, (long)HW*CC, 0,
        nullptr, nullptr, nullptr, 1.f);

    // out = att @ Wp + bp + x (fp32)
    gemm_mma<<<dim3(CC/TN, NPIX/TM, 1), 256, GEMM_DSMEM>>>(
        att, wpt, CC, CC, CC/TK, 0, 0, 0, out, CC, 0, 1, bp, nullptr, x, 1.f);
}